// round 4
// baseline (speedup 1.0000x reference)
#include <cuda_runtime.h>
#include <math.h>

typedef unsigned long long ull;

#define BATCH 64
#define SEQ 256
#define EMBED 512
#define HIDDEN 1024
#define GATES (4*HIDDEN)
#define MTOT (BATCH*SEQ)   // 16384
#define NBLK 128
#define TPB 256

// Scratch (allocation-free rule: __device__ globals)
__device__ float g_Xg[(size_t)MTOT * GATES];     // x@W_ih^T + b_ih + b_hh
__device__ float g_Hout[(size_t)MTOT * HIDDEN];  // all h_t, row = b*SEQ+t
__device__ float g_hA[HIDDEN * BATCH];           // h transposed [k][b]
__device__ float g_hB[HIDDEN * BATCH];
__device__ unsigned g_bar;

// ---- smem layout of persistent kernel (float offsets) ----
#define OFF_W    0                     // 32768 floats (128KB): sW[k][32]
#define OFF_HB   32768                 // 8192 floats (32KB): h chunk [kk][64]
#define OFF_X    40960                 // 2048 floats: sX[b][32]
#define OFF_G    43008                 // 2048 floats: sG[r][64]
#define OFF_RED  45056                 // 2048 floats = 1024 ull
#define SMEM_FLOATS 47104
#define SMEM_BYTES (SMEM_FLOATS*4)     // 188416

__device__ __forceinline__ void fma2(ull& a, ull b, ull c) {
    asm("fma.rn.f32x2 %0, %1, %2, %0;" : "+l"(a) : "l"(b), "l"(c));
}
__device__ __forceinline__ void add2(ull& a, ull b) {
    asm("add.rn.f32x2 %0, %0, %1;" : "+l"(a) : "l"(b));
}
__device__ __forceinline__ ull splat2(float w) {
    ull r; unsigned u = __float_as_uint(w);
    asm("mov.b64 %0, {%1, %1};" : "=l"(r) : "r"(u));
    return r;
}
__device__ __forceinline__ float sigf(float x) { return 1.0f / (1.0f + __expf(-x)); }

__global__ void zero_state_kernel() {
    int i = blockIdx.x * blockDim.x + threadIdx.x;
    if (i < HIDDEN * BATCH) g_hA[i] = 0.0f;
    if (i == 0) g_bar = 0u;
}

// ---------------- fp32 SGEMM (unchanged from R1, known-correct) ----------------
__global__ __launch_bounds__(256, 2)
void sgemm_bias(const float* __restrict__ A, const float* __restrict__ Bw,
                const float* __restrict__ bias1, const float* __restrict__ bias2,
                float* __restrict__ C, int M, int N, int K)
{
    __shared__ float As[8][128];
    __shared__ float Bs[8][128];
    const int m0 = blockIdx.y * 128;
    const int n0 = blockIdx.x * 128;
    const int tid = threadIdx.x;
    const int row = tid >> 1;
    const int kq  = (tid & 1) * 4;
    const int tx = tid & 15;
    const int ty = tid >> 4;

    float acc[8][8];
#pragma unroll
    for (int i = 0; i < 8; i++)
#pragma unroll
        for (int j = 0; j < 8; j++) acc[i][j] = 0.0f;

    const float* Arow = A + (size_t)(m0 + row) * K + kq;
    const float* Brow = Bw + (size_t)(n0 + row) * K + kq;

    for (int k0 = 0; k0 < K; k0 += 8) {
        float4 a4 = *(const float4*)(Arow + k0);
        float4 b4 = *(const float4*)(Brow + k0);
        As[kq+0][row] = a4.x; As[kq+1][row] = a4.y; As[kq+2][row] = a4.z; As[kq+3][row] = a4.w;
        Bs[kq+0][row] = b4.x; Bs[kq+1][row] = b4.y; Bs[kq+2][row] = b4.z; Bs[kq+3][row] = b4.w;
        __syncthreads();
#pragma unroll
        for (int kk = 0; kk < 8; kk++) {
            const float4 a0 = *(const float4*)&As[kk][ty*8];
            const float4 a1 = *(const float4*)&As[kk][ty*8+4];
            const float4 b0 = *(const float4*)&Bs[kk][tx*8];
            const float4 b1 = *(const float4*)&Bs[kk][tx*8+4];
            const float ar[8] = {a0.x,a0.y,a0.z,a0.w,a1.x,a1.y,a1.z,a1.w};
            const float br[8] = {b0.x,b0.y,b0.z,b0.w,b1.x,b1.y,b1.z,b1.w};
#pragma unroll
            for (int i = 0; i < 8; i++)
#pragma unroll
                for (int j = 0; j < 8; j++) acc[i][j] += ar[i] * br[j];
        }
        __syncthreads();
    }

    float bb[8];
#pragma unroll
    for (int j = 0; j < 8; j++) {
        int n = n0 + tx*8 + j;
        float s = bias1 ? bias1[n] : 0.0f;
        if (bias2) s += bias2[n];
        bb[j] = s;
    }
#pragma unroll
    for (int i = 0; i < 8; i++) {
        int m = m0 + ty*8 + i;
        float* Crow = C + (size_t)m * N + n0 + tx*8;
#pragma unroll
        for (int j = 0; j < 8; j++) Crow[j] = acc[i][j] + bb[j];
    }
}

// ---------------- persistent LSTM recurrence ----------------
// 128 blocks x 256 threads, 1 block/SM. Block owns hidden units j0..j0+7,
// i.e. gate rows {g*1024 + j0 + jj}, whose W_hh slice (32 x 1024) lives in
// SMEM for all 256 steps. GEMM: k-split 2 (khalf), thread = 1 row x 8 b-pairs,
// f32x2 accumulators. h streamed in 128-k chunks with register prefetch.
__global__ __launch_bounds__(TPB, 1)
void lstm_persist(const float* __restrict__ Xg, const float* __restrict__ Whh,
                  float* __restrict__ hA, float* __restrict__ hB,
                  float* __restrict__ Hout)
{
    extern __shared__ float sm[];
    float* sW  = sm + OFF_W;
    float* sH  = sm + OFF_HB;
    float* sX  = sm + OFF_X;
    float* sG  = sm + OFF_G;
    ull*   sRd = (ull*)(sm + OFF_RED);

    const int tid = threadIdx.x;
    const int j0 = blockIdx.x * 8;

    // ---- load W_hh slice -> sW[k][r], r = g*8+jj ----
    {
        const int r = tid >> 3;             // 0..31
        const int kpart = tid & 7;          // 0..7 (128 k each)
        const int grow = (r >> 3) * HIDDEN + j0 + (r & 7);
        const float* src = Whh + (size_t)grow * HIDDEN + kpart * 128;
#pragma unroll 4
        for (int kk = 0; kk < 128; kk += 4) {
            float4 v = *(const float4*)(src + kk);
            int kb = kpart * 128 + kk;
            sW[(kb+0)*32 + r] = v.x;
            sW[(kb+1)*32 + r] = v.y;
            sW[(kb+2)*32 + r] = v.z;
            sW[(kb+3)*32 + r] = v.w;
        }
    }
    __syncthreads();

    // GEMM role
    const int khalf = tid >> 7;             // 0/1
    const int r  = (tid >> 2) & 31;         // gate row 0..31
    const int bq = tid & 3;                 // batch quarter (16 b)
    // epilogue role
    const int be = tid >> 2;                // batch 0..63
    const int jp = tid & 3;                 // j-pair 0..3

    float c0 = 0.0f, c1 = 0.0f;             // cell state (register-resident)
    unsigned target = 0;

    for (int t = 0; t < SEQ; t++) {
        const float* hprev = (t & 1) ? hB : hA;
        float*       hnext = (t & 1) ? hA : hB;

        // Xg prefetch (independent of barrier; Xg is constant)
        const float* xsrc = Xg + ((size_t)(be * SEQ + t)) * GATES + jp * HIDDEN + j0;
        float4 xv0 = __ldg((const float4*)xsrc);
        float4 xv1 = __ldg((const float4*)(xsrc + 4));

        // ---- grid barrier: h writes of step t-1 globally visible ----
        __threadfence();
        __syncthreads();
        target += NBLK;
        if (tid == 0) {
            atomicAdd(&g_bar, 1u);
            while (atomicAdd(&g_bar, 0u) < target) __nanosleep(64);
        }
        __syncthreads();

        // stage Xg tile: sX[b][g*8+jj]
        *(float4*)&sX[be*32 + jp*8]     = xv0;
        *(float4*)&sX[be*32 + jp*8 + 4] = xv1;

        // ---- GEMM: gates += W_hh[32 rows] @ h ----
        ull acc[8];
#pragma unroll
        for (int p = 0; p < 8; p++) acc[p] = 0ull;

        // prefetch chunk 0 (h must be read L1-bypassed: cross-SM producer)
        float4 pre[8];
#pragma unroll
        for (int i = 0; i < 8; i++)
            pre[i] = __ldcg((const float4*)hprev + i*256 + tid);

        for (int kc = 0; kc < 8; kc++) {
#pragma unroll
            for (int i = 0; i < 8; i++)
                ((float4*)sH)[i*256 + tid] = pre[i];
            __syncthreads();
            if (kc < 7) {
                const float4* nsrc = (const float4*)(hprev + (kc+1)*128*64);
#pragma unroll
                for (int i = 0; i < 8; i++)
                    pre[i] = __ldcg(nsrc + i*256 + tid);
            }
            const float* wk = sW + (kc*128 + khalf*64)*32 + r;
            const float* hk = sH + khalf*64*64 + bq*16;
#pragma unroll 4
            for (int kk = 0; kk < 64; kk++) {
                ull ws = splat2(wk[kk*32]);
                const ulonglong2* hp = (const ulonglong2*)(hk + kk*64);
                ulonglong2 h01 = hp[0];
                ulonglong2 h23 = hp[1];
                ulonglong2 h45 = hp[2];
                ulonglong2 h67 = hp[3];
                fma2(acc[0], ws, h01.x);
                fma2(acc[1], ws, h01.y);
                fma2(acc[2], ws, h23.x);
                fma2(acc[3], ws, h23.y);
                fma2(acc[4], ws, h45.x);
                fma2(acc[5], ws, h45.y);
                fma2(acc[6], ws, h67.x);
                fma2(acc[7], ws, h67.y);
            }
            __syncthreads();
        }

        // ---- k-split reduction + Xg add -> sG[r][b] ----
        if (khalf == 1) {
#pragma unroll
            for (int p = 0; p < 8; p++) sRd[(tid & 127)*8 + p] = acc[p];
        }
        __syncthreads();
        if (khalf == 0) {
            const int b0 = bq * 16;
#pragma unroll
            for (int p = 0; p < 8; p++) {
                add2(acc[p], sRd[tid*8 + p]);
                union { ull u; float2 f; } v; v.u = acc[p];
                v.f.x += sX[(b0 + 2*p  )*32 + r];
                v.f.y += sX[(b0 + 2*p+1)*32 + r];
                *(float2*)&sG[r*64 + b0 + 2*p] = v.f;
            }
        }
        __syncthreads();

        // ---- elementwise LSTM update (thread: batch be, j-pair jp) ----
        float hvq[2];
#pragma unroll
        for (int q = 0; q < 2; q++) {
            int jl = jp*2 + q;
            float xi = sG[( 0 + jl)*64 + be];
            float xf = sG[( 8 + jl)*64 + be];
            float xg = sG[(16 + jl)*64 + be];
            float xo = sG[(24 + jl)*64 + be];
            float cold = q ? c1 : c0;
            float cn = sigf(xf) * cold + sigf(xi) * tanhf(xg);
            if (q) c1 = cn; else c0 = cn;
            hvq[q] = sigf(xo) * tanhf(cn);
            hnext[(j0 + jl)*64 + be] = hvq[q];
        }
        *(float2*)&Hout[((size_t)(be*SEQ + t))*HIDDEN + j0 + jp*2] =
            make_float2(hvq[0], hvq[1]);
    }
}

extern "C" void kernel_launch(void* const* d_in, const int* in_sizes, int n_in,
                              void* d_out, int out_size)
{
    const float* embedded = (const float*)d_in[0];  // [B,T,E]
    const float* W_ih     = (const float*)d_in[1];  // [4H,E]
    const float* W_hh     = (const float*)d_in[2];  // [4H,H]
    const float* b_ih     = (const float*)d_in[3];  // [4H]
    const float* b_hh     = (const float*)d_in[4];  // [4H]
    const float* W_fc     = (const float*)d_in[5];  // [H,H]
    const float* b_fc     = (const float*)d_in[6];  // [H]
    float* out = (float*)d_out;                     // [B,T,H]

    float *dXg, *dHout, *dhA, *dhB;
    cudaGetSymbolAddress((void**)&dXg,   g_Xg);
    cudaGetSymbolAddress((void**)&dHout, g_Hout);
    cudaGetSymbolAddress((void**)&dhA,   g_hA);
    cudaGetSymbolAddress((void**)&dhB,   g_hB);

    cudaFuncSetAttribute(lstm_persist,
                         cudaFuncAttributeMaxDynamicSharedMemorySize, SMEM_BYTES);

    // 1. zero h0 + barrier counter
    zero_state_kernel<<<(HIDDEN*BATCH + 255)/256, 256>>>();

    // 2. Xg = embedded @ W_ih^T + b_ih + b_hh   (M=16384, N=4096, K=512)
    {
        dim3 grid(GATES/128, MTOT/128);
        sgemm_bias<<<grid, 256>>>(embedded, W_ih, b_ih, b_hh, dXg, MTOT, GATES, EMBED);
    }

    // 3. recurrence: single persistent kernel
    lstm_persist<<<NBLK, TPB, SMEM_BYTES>>>(dXg, W_hh, dhA, dhB, dHout);

    // 4. out = Hout @ W_fc^T + b_fc   (M=16384, N=1024, K=1024)
    {
        dim3 grid(HIDDEN/128, MTOT/128);
        sgemm_bias<<<grid, 256>>>(dHout, W_fc, b_fc, nullptr, out, MTOT, HIDDEN, HIDDEN);
    }
}

// round 6
// speedup vs baseline: 3.5165x; 3.5165x over previous
#include <cuda_runtime.h>
#include <math.h>

typedef unsigned long long ull;

#define BATCH 64
#define SEQ 256
#define EMBED 512
#define HIDDEN 1024
#define GATES (4*HIDDEN)
#define MTOT (BATCH*SEQ)   // 16384
#define NBLK 128
#define TPB 256

// Scratch (allocation-free rule: __device__ globals)
__device__ float g_Xg[(size_t)MTOT * GATES];     // x@W_ih^T + b_ih + b_hh
__device__ float g_Hout[(size_t)MTOT * HIDDEN];  // all h_t, row = b*SEQ+t
__device__ float g_hA[HIDDEN * BATCH];           // h transposed [k][b]
__device__ float g_hB[HIDDEN * BATCH];
__device__ unsigned g_bar;

// ---- smem layout of persistent kernel (float offsets) ----
#define OFF_W    0                     // 32768 floats (128KB): sW[k][32]
#define OFF_H0   32768                 // 4096 floats: h chunk buf0 [64k][64b]
#define OFF_H1   36864                 // 4096 floats: h chunk buf1
#define OFF_X    40960                 // 2048 floats: sX[b][32]
#define OFF_G    43008                 // 2048 floats: sG[r][64]
#define SMEM_FLOATS 45056
#define SMEM_BYTES (SMEM_FLOATS*4)     // 180224

__device__ __forceinline__ void fma2(ull& a, ull b, ull c) {
    asm("fma.rn.f32x2 %0, %1, %2, %0;" : "+l"(a) : "l"(b), "l"(c));
}
__device__ __forceinline__ float sigf(float x) { return 1.0f / (1.0f + __expf(-x)); }

__global__ void zero_state_kernel() {
    int i = blockIdx.x * blockDim.x + threadIdx.x;
    if (i < HIDDEN * BATCH) g_hA[i] = 0.0f;
    if (i == 0) g_bar = 0u;
}

__global__ void dummy_kernel() {}

// ---------------- f32x2 SGEMM: C[M,N] = A[M,K]@B[N,K]^T + bias ----------------
// BM=BN=128, BK=8, 256 threads, micro 8m x 8n (4 n-pairs as f32x2).
__global__ __launch_bounds__(256, 2)
void sgemm2(const float* __restrict__ A, const float* __restrict__ Bw,
            const float* __restrict__ bias1, const float* __restrict__ bias2,
            float* __restrict__ C, int M, int N, int K)
{
    __shared__ float As2[8][256];   // A values duplicated {a,a}
    __shared__ float Bs[8][128];
    const int m0 = blockIdx.y * 128;
    const int n0 = blockIdx.x * 128;
    const int tid = threadIdx.x;
    const int row = tid >> 1;          // 0..127
    const int kq  = (tid & 1) * 4;     // 0 or 4
    const int tx = tid & 15;           // n micro group (8 n = 4 pairs)
    const int ty = tid >> 4;           // m micro group (8 m)

    ull acc[8][4];
#pragma unroll
    for (int i = 0; i < 8; i++)
#pragma unroll
        for (int j = 0; j < 4; j++) acc[i][j] = 0ull;

    const float* Arow = A + (size_t)(m0 + row) * K + kq;
    const float* Brow = Bw + (size_t)(n0 + row) * K + kq;

    for (int k0 = 0; k0 < K; k0 += 8) {
        float4 a4 = *(const float4*)(Arow + k0);
        float4 b4 = *(const float4*)(Brow + k0);
        As2[kq+0][row*2] = a4.x; As2[kq+0][row*2+1] = a4.x;
        As2[kq+1][row*2] = a4.y; As2[kq+1][row*2+1] = a4.y;
        As2[kq+2][row*2] = a4.z; As2[kq+2][row*2+1] = a4.z;
        As2[kq+3][row*2] = a4.w; As2[kq+3][row*2+1] = a4.w;
        Bs[kq+0][row] = b4.x; Bs[kq+1][row] = b4.y; Bs[kq+2][row] = b4.z; Bs[kq+3][row] = b4.w;
        __syncthreads();
#pragma unroll
        for (int kk = 0; kk < 8; kk++) {
            ulonglong2 a01 = *(const ulonglong2*)&As2[kk][ty*16];
            ulonglong2 a23 = *(const ulonglong2*)&As2[kk][ty*16+4];
            ulonglong2 a45 = *(const ulonglong2*)&As2[kk][ty*16+8];
            ulonglong2 a67 = *(const ulonglong2*)&As2[kk][ty*16+12];
            ulonglong2 b01 = *(const ulonglong2*)&Bs[kk][tx*8];
            ulonglong2 b23 = *(const ulonglong2*)&Bs[kk][tx*8+4];
            ull av[8] = {a01.x,a01.y,a23.x,a23.y,a45.x,a45.y,a67.x,a67.y};
            ull bv[4] = {b01.x,b01.y,b23.x,b23.y};
#pragma unroll
            for (int i = 0; i < 8; i++)
#pragma unroll
                for (int j = 0; j < 4; j++) fma2(acc[i][j], av[i], bv[j]);
        }
        __syncthreads();
    }

    float bb[8];
#pragma unroll
    for (int j = 0; j < 8; j++) {
        int n = n0 + tx*8 + j;
        float s = bias1 ? bias1[n] : 0.0f;
        if (bias2) s += bias2[n];
        bb[j] = s;
    }
#pragma unroll
    for (int i = 0; i < 8; i++) {
        int m = m0 + ty*8 + i;
        float* Crow = C + (size_t)m * N + n0 + tx*8;
#pragma unroll
        for (int j = 0; j < 4; j++) {
            union { ull u; float2 f; } v; v.u = acc[i][j];
            v.f.x += bb[j*2];
            v.f.y += bb[j*2+1];
            *(float2*)&Crow[j*2] = v.f;
        }
    }
}

// ---------------- persistent LSTM recurrence (plain FFMA) ----------------
// 128 blocks x 256 threads, 1 block/SM. Block owns hidden units j0..j0+7
// => gate rows {g*1024 + j0 + jj} (32 rows), W_hh slice resident in SMEM.
// Thread GEMM tile: 2 rows x 4 batch over full K. h streamed in 64-k chunks,
// double-buffered in SMEM with 4xfloat4 register prefetch.
__global__ __launch_bounds__(TPB, 1)
void lstm_persist(const float* __restrict__ Xg, const float* __restrict__ Whh,
                  float* __restrict__ hA, float* __restrict__ hB,
                  float* __restrict__ Hout)
{
    extern __shared__ float sm[];
    float* sW  = sm + OFF_W;
    float* sX  = sm + OFF_X;
    float* sG  = sm + OFF_G;

    const int tid = threadIdx.x;
    const int j0 = blockIdx.x * 8;

    // ---- load W_hh slice -> sW[k][r], r = g*8+jj (once) ----
    {
        const int r = tid >> 3;             // 0..31
        const int kpart = tid & 7;          // 0..7
        const int grow = (r >> 3) * HIDDEN + j0 + (r & 7);
        const float* src = Whh + (size_t)grow * HIDDEN + kpart * 128;
#pragma unroll 4
        for (int kk = 0; kk < 128; kk += 4) {
            float4 v = *(const float4*)(src + kk);
            int kb = kpart * 128 + kk;
            sW[(kb+0)*32 + r] = v.x;
            sW[(kb+1)*32 + r] = v.y;
            sW[(kb+2)*32 + r] = v.z;
            sW[(kb+3)*32 + r] = v.w;
        }
    }
    __syncthreads();

    // GEMM roles
    const int ty = tid >> 4;                // 0..15 -> rows ty*2, ty*2+1
    const int tx = tid & 15;                // 0..15 -> batches tx*4..+3
    // epilogue roles
    const int be = tid >> 2;                // batch 0..63
    const int jp = tid & 3;                 // j-pair 0..3

    float c0 = 0.0f, c1 = 0.0f;             // cell state (register-resident)
    unsigned target = 0;

    for (int t = 0; t < SEQ; t++) {
        const float* hprev = (t & 1) ? hB : hA;
        float*       hnext = (t & 1) ? hA : hB;

        // Xg prefetch (Xg constant; safe before barrier)
        const float* xsrc = Xg + ((size_t)(be * SEQ + t)) * GATES + jp * HIDDEN + j0;
        float4 xv0 = __ldg((const float4*)xsrc);
        float4 xv1 = __ldg((const float4*)(xsrc + 4));

        // ---- grid barrier: h writes of step t-1 globally visible ----
        __threadfence();
        __syncthreads();
        target += NBLK;
        if (tid == 0) {
            atomicAdd(&g_bar, 1u);
            volatile unsigned* gb = &g_bar;
            while (*gb < target) __nanosleep(32);
        }
        __syncthreads();

        // stage Xg tile: sX[b][g*8+jj]
        *(float4*)&sX[be*32 + jp*8]     = xv0;
        *(float4*)&sX[be*32 + jp*8 + 4] = xv1;

        // ---- GEMM: 32 gate rows x 64 batch over K=1024 ----
        float acc[2][4];
#pragma unroll
        for (int i = 0; i < 2; i++)
#pragma unroll
            for (int j = 0; j < 4; j++) acc[i][j] = 0.0f;

        // prefetch chunk 0 (L1-bypass: h produced by other SMs)
        float4 p[4];
#pragma unroll
        for (int i = 0; i < 4; i++)
            p[i] = __ldcg((const float4*)hprev + i*256 + tid);
        // store chunk 0
        {
            float* buf = sm + OFF_H0;
#pragma unroll
            for (int i = 0; i < 4; i++)
                ((float4*)buf)[i*256 + tid] = p[i];
        }
        __syncthreads();

        const float2* w2 = (const float2*)sW + ty;   // [k*16 + ty]

        for (int kc = 0; kc < 16; kc++) {
            if (kc < 15) {
                const float4* nsrc = (const float4*)(hprev + (kc+1)*64*64);
#pragma unroll
                for (int i = 0; i < 4; i++)
                    p[i] = __ldcg(nsrc + i*256 + tid);
            }
            const float* buf = sm + ((kc & 1) ? OFF_H1 : OFF_H0);
            const float4* h4p = (const float4*)buf + tx;
#pragma unroll 8
            for (int kl = 0; kl < 64; kl++) {
                float2 w = w2[(kc*64 + kl)*16];
                float4 h = h4p[kl*16];
                acc[0][0] += w.x * h.x;  acc[0][1] += w.x * h.y;
                acc[0][2] += w.x * h.z;  acc[0][3] += w.x * h.w;
                acc[1][0] += w.y * h.x;  acc[1][1] += w.y * h.y;
                acc[1][2] += w.y * h.z;  acc[1][3] += w.y * h.w;
            }
            if (kc < 15) {
                float* nbuf = sm + ((kc & 1) ? OFF_H0 : OFF_H1);
#pragma unroll
                for (int i = 0; i < 4; i++)
                    ((float4*)nbuf)[i*256 + tid] = p[i];
            }
            __syncthreads();
        }

        // ---- gates = acc + Xg -> sG[r][64] ----
        {
            const int b0 = tx * 4;
#pragma unroll
            for (int i = 0; i < 2; i++) {
                int r = ty*2 + i;
                int g = r >> 3, jj = r & 7;
                float4 o;
                o.x = acc[i][0] + sX[(b0+0)*32 + g*8 + jj];
                o.y = acc[i][1] + sX[(b0+1)*32 + g*8 + jj];
                o.z = acc[i][2] + sX[(b0+2)*32 + g*8 + jj];
                o.w = acc[i][3] + sX[(b0+3)*32 + g*8 + jj];
                *(float4*)&sG[r*64 + b0] = o;
            }
        }
        __syncthreads();

        // ---- elementwise LSTM update (thread: batch be, j-pair jp) ----
        float hvq[2];
#pragma unroll
        for (int q = 0; q < 2; q++) {
            int jl = jp*2 + q;
            float xi = sG[( 0 + jl)*64 + be];
            float xf = sG[( 8 + jl)*64 + be];
            float xg = sG[(16 + jl)*64 + be];
            float xo = sG[(24 + jl)*64 + be];
            float cold = q ? c1 : c0;
            float cn = sigf(xf) * cold + sigf(xi) * tanhf(xg);
            if (q) c1 = cn; else c0 = cn;
            hvq[q] = sigf(xo) * tanhf(cn);
            hnext[(j0 + jl)*64 + be] = hvq[q];
        }
        *(float2*)&Hout[((size_t)(be*SEQ + t))*HIDDEN + j0 + jp*2] =
            make_float2(hvq[0], hvq[1]);
    }
}

extern "C" void kernel_launch(void* const* d_in, const int* in_sizes, int n_in,
                              void* d_out, int out_size)
{
    const float* embedded = (const float*)d_in[0];  // [B,T,E]
    const float* W_ih     = (const float*)d_in[1];  // [4H,E]
    const float* W_hh     = (const float*)d_in[2];  // [4H,H]
    const float* b_ih     = (const float*)d_in[3];  // [4H]
    const float* b_hh     = (const float*)d_in[4];  // [4H]
    const float* W_fc     = (const float*)d_in[5];  // [H,H]
    const float* b_fc     = (const float*)d_in[6];  // [H]
    float* out = (float*)d_out;                     // [B,T,H]

    float *dXg, *dHout, *dhA, *dhB;
    cudaGetSymbolAddress((void**)&dXg,   g_Xg);
    cudaGetSymbolAddress((void**)&dHout, g_Hout);
    cudaGetSymbolAddress((void**)&dhA,   g_hA);
    cudaGetSymbolAddress((void**)&dhB,   g_hB);

    cudaFuncSetAttribute(lstm_persist,
                         cudaFuncAttributeMaxDynamicSharedMemorySize, SMEM_BYTES);

    // launch #1: zero h0 + barrier counter
    zero_state_kernel<<<(HIDDEN*BATCH + 255)/256, 256>>>();

    // launch #2: Xg = embedded @ W_ih^T + b_ih + b_hh (M=16384,N=4096,K=512)
    {
        dim3 grid(GATES/128, MTOT/128);
        sgemm2<<<grid, 256>>>(embedded, W_ih, b_ih, b_hh, dXg, MTOT, GATES, EMBED);
    }

    // launches #3-#5: position lstm_persist as the 6th launch for ncu (-s 5)
    dummy_kernel<<<1, 1>>>();
    dummy_kernel<<<1, 1>>>();
    dummy_kernel<<<1, 1>>>();

    // launch #6: recurrence (single persistent kernel)
    lstm_persist<<<NBLK, TPB, SMEM_BYTES>>>(dXg, W_hh, dhA, dhB, dHout);

    // launch #7: out = Hout @ W_fc^T + b_fc (M=16384,N=1024,K=1024)
    {
        dim3 grid(HIDDEN/128, MTOT/128);
        sgemm2<<<grid, 256>>>(dHout, W_fc, b_fc, nullptr, out, MTOT, HIDDEN, HIDDEN);
    }
}